// round 7
// baseline (speedup 1.0000x reference)
#include <cuda_runtime.h>
#include <math.h>

// ---------------------------------------------------------------------------
// Problem constants
// ---------------------------------------------------------------------------
#define TT   1024
#define BB   128
#define HH   256
#define EE   58
#define OUTD 33
#define BH   (BB*HH)                 // 32768
#define HN_OFF (TT*BB*OUTD)          // 4325376
#define CN_OFF (HN_OFF + 2*BH)       // 4390912

// Decomposition: 4 batch groups (32 rows) x 32 hidden groups (8 units) = 128 CTAs
#define GBN 4
#define MB  32
#define NTH 256
#define AS  516       // A staging stride (floats)
#define GS  33        // gates tile stride (conflict-free scalar access)

// Shared memory layout (float offsets)
// W0: K=320 (64 x-pad + 256 h), k-pair interleaved [kp][col*2+(k&1)]: 160*64
// W1: K=512 (256 y0 + 256 h1): 256*64
#define OFF_W0 0
#define OFF_W1 10240
#define OFF_A  26624          // 32*516 = 16512
#define OFF_G  43136          // 32*33 = 1056
#define OFF_B0 44192
#define OFF_B1 44224
#define SMEM_FLOATS 44256
#define SMEM_BYTES  (SMEM_FLOATS*4)   // 177024

#define PS 260
#define PROJ_SMEM ((33*PS + 32*PS + 64)*4)

// ---------------------------------------------------------------------------
// Global scratch (static __device__ arrays: allocation-free)
// ---------------------------------------------------------------------------
__device__ __align__(16) float g_h0[2][BH];
__device__ __align__(16) float g_h1[2][BH];
__device__ __align__(16) float g_y1[(size_t)TT * BH];
__device__ unsigned g_bar[GBN];

// ---------------------------------------------------------------------------
__global__ void reset_kernel(const float* __restrict__ h0in) {
    int i = blockIdx.x * blockDim.x + threadIdx.x;
    if (i < BH) {
        g_h0[0][i] = h0in[i];
        g_h1[0][i] = h0in[BH + i];
    }
    if (i < GBN) g_bar[i] = 0u;
}

// ---------------------------------------------------------------------------
// Packed f32x2 FMA: c.lo += a.lo*b.lo ; c.hi += a.hi*b.hi
// ---------------------------------------------------------------------------
#define FFMA2(c, a, b) asm("fma.rn.f32x2 %0, %1, %2, %0;" : "+l"(c) : "l"(a), "l"(b))

__device__ __forceinline__ float pair_sum(unsigned long long p) {
    return __uint_as_float((unsigned)p) + __uint_as_float((unsigned)(p >> 32));
}

// GEMM: acc[4] (f32x2 pairs) over K. One A row per thread, 4 gate cols.
// W layout: [kp][32 cols x 2]; thread covers cols tx*4..tx*4+3 (floats tx*8..+8).
// Lane remap guarantees conflict-free quarter-warp LDS:
//   W: 4 distinct 16B (tx 0..3 | 4..7) broadcast over 2 rows -> 1 phase
//   A: 2 distinct 16B rows broadcast over 4 -> 1 phase
__device__ __forceinline__ void gemm_packed(const float* __restrict__ Arow,
                                            const float* __restrict__ Wb,
                                            int tx, int K,
                                            unsigned long long acc[4])
{
    const float* wp = Wb + tx*8;
#pragma unroll 4
    for (int k = 0; k < K; k += 4) {
        ulonglong2 a = *reinterpret_cast<const ulonglong2*>(Arow + k);
        const float* w = wp + (k >> 1) * 64;
        ulonglong2 w0a = *reinterpret_cast<const ulonglong2*>(w);
        ulonglong2 w0b = *reinterpret_cast<const ulonglong2*>(w + 4);
        ulonglong2 w1a = *reinterpret_cast<const ulonglong2*>(w + 64);
        ulonglong2 w1b = *reinterpret_cast<const ulonglong2*>(w + 68);

        FFMA2(acc[0], a.x, w0a.x); FFMA2(acc[1], a.x, w0a.y);
        FFMA2(acc[2], a.x, w0b.x); FFMA2(acc[3], a.x, w0b.y);
        FFMA2(acc[0], a.y, w1a.x); FFMA2(acc[1], a.y, w1a.y);
        FFMA2(acc[2], a.y, w1b.x); FFMA2(acc[3], a.y, w1b.y);
    }
}

__device__ __forceinline__ float fsigmoid(float x) {
    return __fdividef(1.0f, 1.0f + __expf(-x));
}
__device__ __forceinline__ float ftanh(float x) {
    float xc = fminf(fmaxf(x, -15.0f), 15.0f);
    float e = __expf(2.0f * xc);
    return __fdividef(e - 1.0f, e + 1.0f);
}

// Batch-group spin barrier (monotonic counter; 32 CTAs/group, all resident)
__device__ __forceinline__ void group_barrier(int gb, unsigned target) {
    __threadfence();
    __syncthreads();
    if (threadIdx.x == 0) {
        atomicAdd(&g_bar[gb], 1u);
        while (*((volatile unsigned*)&g_bar[gb]) < target) { }
        __threadfence();
    }
    __syncthreads();
}

// ---------------------------------------------------------------------------
// Persistent 2-layer LSTM: grid 128 CTAs x 256 threads
// ---------------------------------------------------------------------------
__global__ __launch_bounds__(NTH, 1)
void lstm_persistent(const float* __restrict__ x,
                     const float* __restrict__ c0in,
                     const float* __restrict__ Wih0, const float* __restrict__ Whh0,
                     const float* __restrict__ bih0, const float* __restrict__ bhh0,
                     const float* __restrict__ Wih1, const float* __restrict__ Whh1,
                     const float* __restrict__ bih1, const float* __restrict__ bhh1,
                     float* __restrict__ out)
{
    extern __shared__ float sm[];
    float* W0s = sm + OFF_W0;
    float* W1s = sm + OFF_W1;
    float* Asm = sm + OFF_A;
    float* Gs  = sm + OFF_G;
    float* B0s = sm + OFF_B0;
    float* B1s = sm + OFF_B1;

    const int tid = threadIdx.x;
    const int gb  = blockIdx.x >> 5;
    const int gn  = blockIdx.x & 31;
    const int b0  = gb * MB;

    // ---- stage weights (once), k-pair interleaved: [kp][j*2 + (k&1)] ----
    for (int idx = tid; idx < 32*320; idx += NTH) {
        int j = idx / 320, k = idx % 320;
        int gc = ((j >> 3) << 8) + (gn << 3) + (j & 7);
        float v;
        if (k < 64) v = (k < EE) ? Wih0[gc*EE + k] : 0.0f;
        else        v = Whh0[gc*HH + (k - 64)];
        W0s[(k >> 1)*64 + j*2 + (k & 1)] = v;
    }
    for (int idx = tid; idx < 32*512; idx += NTH) {
        int j = idx / 512, k = idx % 512;
        int gc = ((j >> 3) << 8) + (gn << 3) + (j & 7);
        float v = (k < 256) ? Wih1[gc*HH + k] : Whh1[gc*HH + (k - 256)];
        W1s[(k >> 1)*64 + j*2 + (k & 1)] = v;
    }
    if (tid < 32) {
        int gc = ((tid >> 3) << 8) + (gn << 3) + (tid & 7);
        B0s[tid] = bih0[gc] + bhh0[gc];
        B1s[tid] = bih1[gc] + bhh1[gc];
    }

    // elementwise mapping: one (batch eb, hidden q) per thread
    const int eb = tid & 31, q = tid >> 5;       // q 0..7
    const int hg = (gn << 3) + q;
    const int bg = b0 + eb;
    float c0r = c0in[bg*HH + hg];
    float c1r = c0in[BH + bg*HH + hg];
    float hl0 = 0.0f, hl1 = 0.0f;

    // GEMM mapping: conflict-free lane remap.
    // lane bits: [1:0]->tx low, [3:2]->row low, [4]->tx high
    const int lane = tid & 31, warp = tid >> 5;
    const int tx  = (lane & 3) + ((lane & 16) >> 2);   // 0..7 col group
    const int row = warp*4 + ((lane >> 2) & 3);        // 0..31 output row
    const float* Arow = Asm + row*AS;

    __syncthreads();

    for (int t = 0; t < TT; ++t) {
        const int rp = t & 1, wp = rp ^ 1;

        // ---- stage 1: A = [x(64, zero-pad) | h0[t-1](256)], batched loads ----
        {
            float xv[8];
#pragma unroll
            for (int i = 0; i < 8; ++i) {
                int idx = tid + i*NTH;
                int m = idx >> 6, e = idx & 63;
                xv[i] = (e < EE) ? x[(size_t)t*BB*EE + (size_t)(b0+m)*EE + e] : 0.0f;
            }
            float4 hv[8];
            const float4* src = reinterpret_cast<const float4*>(&g_h0[rp][b0*HH]);
#pragma unroll
            for (int i = 0; i < 8; ++i) hv[i] = __ldcg(src + tid + i*NTH);
#pragma unroll
            for (int i = 0; i < 8; ++i) {
                int idx = tid + i*NTH;
                int m = idx >> 6, e = idx & 63;
                Asm[m*AS + e] = xv[i];
            }
#pragma unroll
            for (int i = 0; i < 8; ++i) {
                int idx = tid + i*NTH;
                int m = idx >> 6, c = idx & 63;
                *reinterpret_cast<float4*>(&Asm[m*AS + 64 + c*4]) = hv[i];
            }
        }
        __syncthreads();

        // ---- layer 0 GEMM (K=320) ----
        {
            unsigned long long acc[4] = {0,0,0,0};
            gemm_packed(Arow, W0s, tx, 320, acc);
#pragma unroll
            for (int j = 0; j < 4; ++j)
                Gs[row*GS + tx*4 + j] = pair_sum(acc[j]) + B0s[tx*4 + j];
        }
        __syncthreads();

        // ---- layer 0 elementwise: publish h0[t] ----
        {
            float gi = Gs[eb*GS + q];
            float gf = Gs[eb*GS + 8 + q];
            float gg = Gs[eb*GS + 16 + q];
            float go = Gs[eb*GS + 24 + q];
            float iv = fsigmoid(gi), fv = fsigmoid(gf);
            float gv = ftanh(gg),    ov = fsigmoid(go);
            c0r = fv * c0r + iv * gv;
            float hv = ov * ftanh(c0r);
            hl0 = hv;
            __stcg(&g_h0[wp][bg*HH + hg], hv);
        }
        // single barrier per step: orders h0[t] (just written) AND h1[t-1]
        // (written before each CTA's arrival here) before stage-2 reads.
        group_barrier(gb, 32u*(t+1));

        // ---- stage 2: A = [y0 = h0[t] (256) | h1[t-1] (256)], batched ----
        {
            float4 v0[8], v1[8];
            const float4* s0 = reinterpret_cast<const float4*>(&g_h0[wp][b0*HH]);
            const float4* s1 = reinterpret_cast<const float4*>(&g_h1[rp][b0*HH]);
#pragma unroll
            for (int i = 0; i < 8; ++i) v0[i] = __ldcg(s0 + tid + i*NTH);
#pragma unroll
            for (int i = 0; i < 8; ++i) v1[i] = __ldcg(s1 + tid + i*NTH);
#pragma unroll
            for (int i = 0; i < 8; ++i) {
                int idx = tid + i*NTH;
                int m = idx >> 6, c = idx & 63;
                *reinterpret_cast<float4*>(&Asm[m*AS + c*4]) = v0[i];
            }
#pragma unroll
            for (int i = 0; i < 8; ++i) {
                int idx = tid + i*NTH;
                int m = idx >> 6, c = idx & 63;
                *reinterpret_cast<float4*>(&Asm[m*AS + 256 + c*4]) = v1[i];
            }
        }
        __syncthreads();

        // ---- layer 1 GEMM (K=512) ----
        {
            unsigned long long acc[4] = {0,0,0,0};
            gemm_packed(Arow, W1s, tx, 512, acc);
#pragma unroll
            for (int j = 0; j < 4; ++j)
                Gs[row*GS + tx*4 + j] = pair_sum(acc[j]) + B1s[tx*4 + j];
        }
        __syncthreads();

        // ---- layer 1 elementwise: publish h1[t] + y1 ----
        {
            float gi = Gs[eb*GS + q];
            float gf = Gs[eb*GS + 8 + q];
            float gg = Gs[eb*GS + 16 + q];
            float go = Gs[eb*GS + 24 + q];
            float iv = fsigmoid(gi), fv = fsigmoid(gf);
            float gv = ftanh(gg),    ov = fsigmoid(go);
            c1r = fv * c1r + iv * gv;
            float hv = ov * ftanh(c1r);
            hl1 = hv;
            __stcg(&g_h1[wp][bg*HH + hg], hv);
            __stcg(&g_y1[(size_t)t*BH + (size_t)bg*HH + hg], hv);
        }
        // no second barrier: next step's barrier covers h1[t] visibility.
    }

    // ---- final hn / cn ----
    out[HN_OFF +      bg*HH + hg] = hl0;
    out[HN_OFF + BH + bg*HH + hg] = hl1;
    out[CN_OFF +      bg*HH + hg] = c0r;
    out[CN_OFF + BH + bg*HH + hg] = c1r;
}

// ---------------------------------------------------------------------------
// Output projection: out = softplus(y1 @ W_out^T + b_out)
// ---------------------------------------------------------------------------
__global__ __launch_bounds__(128)
void proj_kernel(const float* __restrict__ Wout,
                 const float* __restrict__ bout,
                 float* __restrict__ out)
{
    extern __shared__ float sm[];
    float* ws = sm;
    float* ys = sm + 33*PS;
    float* bs = sm + 33*PS + 32*PS;

    const int tid = threadIdx.x;
    const int t  = blockIdx.x >> 2;
    const int b0 = (blockIdx.x & 3) * 32;

    for (int idx = tid; idx < 33*256; idx += 128) {
        int o = idx >> 8, k = idx & 255;
        ws[o*PS + k] = Wout[idx];
    }
    if (tid < 33) bs[tid] = bout[tid];
    {
        const float* ysrc = &g_y1[(size_t)t*BH + (size_t)b0*HH];
        for (int idx = tid; idx < 32*256; idx += 128) {
            int m = idx >> 8, k = idx & 255;
            ys[m*PS + k] = ysrc[idx];
        }
    }
    __syncthreads();

    for (int oidx = tid; oidx < 33*32; oidx += 128) {
        int o = oidx >> 5, m = oidx & 31;
        const float* yp = &ys[m*PS];
        const float* wpp = &ws[o*PS];
        float s = bs[o];
#pragma unroll 8
        for (int k = 0; k < 256; k += 4) {
            float4 y4 = *reinterpret_cast<const float4*>(yp + k);
            float4 w4 = *reinterpret_cast<const float4*>(wpp + k);
            s += y4.x*w4.x + y4.y*w4.y + y4.z*w4.z + y4.w*w4.w;
        }
        float sp = fmaxf(s, 0.0f) + log1pf(expf(-fabsf(s)));
        out[(size_t)t*BB*OUTD + (size_t)(b0+m)*OUTD + o] = sp;
    }
}

// ---------------------------------------------------------------------------
extern "C" void kernel_launch(void* const* d_in, const int* in_sizes, int n_in,
                              void* d_out, int out_size) {
    (void)in_sizes; (void)n_in; (void)out_size;
    const float* x    = (const float*)d_in[0];
    const float* h0   = (const float*)d_in[1];
    const float* c0   = (const float*)d_in[2];
    const float* Wih0 = (const float*)d_in[3];
    const float* Whh0 = (const float*)d_in[4];
    const float* bih0 = (const float*)d_in[5];
    const float* bhh0 = (const float*)d_in[6];
    const float* Wih1 = (const float*)d_in[7];
    const float* Whh1 = (const float*)d_in[8];
    const float* bih1 = (const float*)d_in[9];
    const float* bhh1 = (const float*)d_in[10];
    const float* Wout = (const float*)d_in[11];
    const float* bout = (const float*)d_in[12];
    float* out = (float*)d_out;

    cudaFuncSetAttribute(lstm_persistent,
                         cudaFuncAttributeMaxDynamicSharedMemorySize, SMEM_BYTES);
    cudaFuncSetAttribute(proj_kernel,
                         cudaFuncAttributeMaxDynamicSharedMemorySize, PROJ_SMEM);

    reset_kernel<<<128, 256>>>(h0);
    lstm_persistent<<<128, NTH, SMEM_BYTES>>>(
        x, c0, Wih0, Whh0, bih0, bhh0, Wih1, Whh1, bih1, bhh1, out);
    proj_kernel<<<4096, 128, PROJ_SMEM>>>(Wout, bout, out);
}

// round 8
// speedup vs baseline: 1.2173x; 1.2173x over previous
#include <cuda_runtime.h>
#include <math.h>

// ---------------------------------------------------------------------------
// Problem constants
// ---------------------------------------------------------------------------
#define TT   1024
#define BB   128
#define HH   256
#define EE   58
#define OUTD 33
#define BH   (BB*HH)                 // 32768
#define HN_OFF (TT*BB*OUTD)          // 4325376
#define CN_OFF (HN_OFF + 2*BH)       // 4390912

// 4 batch groups (32 rows) x 32 hidden groups (8 units) = 128 CTAs
#define GBN 4
#define MB  32
#define NTH 256
#define AS  516       // A staging stride (floats); 4*AS*4B mod 128 = 64 -> CF
#define GS  33        // partial/gate tile stride (odd -> conflict-free scalar)

// Shared memory layout (float offsets)
// W0: K=320, interleaved [kp][jj*16 + cg*4 + q*2 + (k&1)]: 160*64 = 10240
// W1: K=512: 256*64 = 16384
// A : 32*516 = 16512
// GP: 8 K-split partials x (32*33) = 8448
#define OFF_W0 0
#define OFF_W1 10240
#define OFF_A  26624
#define OFF_GP 43136
#define OFF_B0 51584
#define OFF_B1 51616
#define SMEM_FLOATS 51648
#define SMEM_BYTES  (SMEM_FLOATS*4)   // 206592

#define PS 260
#define PROJ_SMEM ((33*PS + 32*PS + 64)*4)

// ---------------------------------------------------------------------------
// Global scratch (static __device__ arrays: allocation-free)
// ---------------------------------------------------------------------------
__device__ __align__(16) float g_h0[2][BH];
__device__ __align__(16) float g_h1[2][BH];
__device__ __align__(16) float g_y1[(size_t)TT * BH];
__device__ unsigned g_bar[GBN];

// ---------------------------------------------------------------------------
__global__ void reset_kernel(const float* __restrict__ h0in) {
    int i = blockIdx.x * blockDim.x + threadIdx.x;
    if (i < BH) {
        g_h0[0][i] = h0in[i];
        g_h1[0][i] = h0in[BH + i];
    }
    if (i < GBN) g_bar[i] = 0u;
}

// ---------------------------------------------------------------------------
// Packed f32x2 FMA: c.lo += a.lo*b.lo ; c.hi += a.hi*b.hi
// ---------------------------------------------------------------------------
#define FFMA2(c, a, b) asm("fma.rn.f32x2 %0, %1, %2, %0;" : "+l"(c) : "l"(a), "l"(b))

__device__ __forceinline__ float pair_sum(unsigned long long p) {
    return __uint_as_float((unsigned)p) + __uint_as_float((unsigned)(p >> 32));
}

// GEMM tile: 4 rows x 8 cols, NIT iterations of 4 k-values.
// Ab: A base for this thread's 4 rows + its K-slice offset.
// Wp: W base + kp-slice*64 + cg*4. acc[i][jj*2+q] for col cg*8+jj*2+q.
template<int NIT>
__device__ __forceinline__ void gemm_tile(const float* __restrict__ Ab,
                                          const float* __restrict__ Wp,
                                          unsigned long long acc[4][8])
{
#pragma unroll 4
    for (int it = 0; it < NIT; ++it) {
        ulonglong2 a[4];
#pragma unroll
        for (int i = 0; i < 4; ++i)
            a[i] = *reinterpret_cast<const ulonglong2*>(Ab + i*AS + it*4);
#pragma unroll
        for (int half = 0; half < 2; ++half) {
            const float* w = Wp + (2*it + half)*64;
            ulonglong2 w0 = *reinterpret_cast<const ulonglong2*>(w);
            ulonglong2 w1 = *reinterpret_cast<const ulonglong2*>(w + 16);
            ulonglong2 w2 = *reinterpret_cast<const ulonglong2*>(w + 32);
            ulonglong2 w3 = *reinterpret_cast<const ulonglong2*>(w + 48);
#pragma unroll
            for (int i = 0; i < 4; ++i) {
                unsigned long long av = half ? a[i].y : a[i].x;
                FFMA2(acc[i][0], av, w0.x); FFMA2(acc[i][1], av, w0.y);
                FFMA2(acc[i][2], av, w1.x); FFMA2(acc[i][3], av, w1.y);
                FFMA2(acc[i][4], av, w2.x); FFMA2(acc[i][5], av, w2.y);
                FFMA2(acc[i][6], av, w3.x); FFMA2(acc[i][7], av, w3.y);
            }
        }
    }
}

__device__ __forceinline__ float fsigmoid(float x) {
    return __fdividef(1.0f, 1.0f + __expf(-x));
}
__device__ __forceinline__ float ftanh(float x) {
    float xc = fminf(fmaxf(x, -15.0f), 15.0f);
    float e = __expf(2.0f * xc);
    return __fdividef(e - 1.0f, e + 1.0f);
}

// Batch-group spin barrier (monotonic counter; 32 CTAs/group, all resident)
__device__ __forceinline__ void group_barrier(int gb, unsigned target) {
    __threadfence();
    __syncthreads();
    if (threadIdx.x == 0) {
        atomicAdd(&g_bar[gb], 1u);
        while (*((volatile unsigned*)&g_bar[gb]) < target) { }
        __threadfence();
    }
    __syncthreads();
}

// ---------------------------------------------------------------------------
// Persistent 2-layer LSTM: grid 128 CTAs x 256 threads
// ---------------------------------------------------------------------------
__global__ __launch_bounds__(NTH, 1)
void lstm_persistent(const float* __restrict__ x,
                     const float* __restrict__ c0in,
                     const float* __restrict__ Wih0, const float* __restrict__ Whh0,
                     const float* __restrict__ bih0, const float* __restrict__ bhh0,
                     const float* __restrict__ Wih1, const float* __restrict__ Whh1,
                     const float* __restrict__ bih1, const float* __restrict__ bhh1,
                     float* __restrict__ out)
{
    extern __shared__ float sm[];
    float* W0s = sm + OFF_W0;
    float* W1s = sm + OFF_W1;
    float* Asm = sm + OFF_A;
    float* GP  = sm + OFF_GP;
    float* B0s = sm + OFF_B0;
    float* B1s = sm + OFF_B1;

    const int tid = threadIdx.x;
    const int gb  = blockIdx.x >> 5;
    const int gn  = blockIdx.x & 31;
    const int b0  = gb * MB;

    // ---- stage weights (once), interleaved layout ----
    for (int idx = tid; idx < 32*320; idx += NTH) {
        int j = idx / 320, k = idx % 320;
        int gc = ((j >> 3) << 8) + (gn << 3) + (j & 7);
        float v;
        if (k < 64) v = (k < EE) ? Wih0[gc*EE + k] : 0.0f;
        else        v = Whh0[gc*HH + (k - 64)];
        W0s[(k >> 1)*64 + ((j & 7) >> 1)*16 + (j >> 3)*4 + (j & 1)*2 + (k & 1)] = v;
    }
    for (int idx = tid; idx < 32*512; idx += NTH) {
        int j = idx / 512, k = idx % 512;
        int gc = ((j >> 3) << 8) + (gn << 3) + (j & 7);
        float v = (k < 256) ? Wih1[gc*HH + k] : Whh1[gc*HH + (k - 256)];
        W1s[(k >> 1)*64 + ((j & 7) >> 1)*16 + (j >> 3)*4 + (j & 1)*2 + (k & 1)] = v;
    }
    if (tid < 32) {
        int gc = ((tid >> 3) << 8) + (gn << 3) + (tid & 7);
        B0s[tid] = bih0[gc] + bhh0[gc];
        B1s[tid] = bih1[gc] + bhh1[gc];
    }

    // elementwise mapping: one (batch eb, hidden unit q) per thread
    const int eb = tid & 31, q = tid >> 5;       // q 0..7
    const int hg = (gn << 3) + q;
    const int bg = b0 + eb;
    float c0r = c0in[bg*HH + hg];
    float c1r = c0in[BH + bg*HH + hg];
    float hl0 = 0.0f, hl1 = 0.0f;

    // GEMM mapping: 8 row-groups (r) x 4 col-groups (cg) x 8 K-splits (ks)
    // lane bits: [1:0]=cg, [2]=r0, [4:3]=ks[1:0]; warp: [1:0]=r[2:1], [2]=ks[2]
    const int lane = tid & 31, warp = tid >> 5;
    const int cg = lane & 3;
    const int rg = (warp & 3)*2 + ((lane >> 2) & 1);   // 0..7, rows 4rg..4rg+3
    const int ks = (warp >> 2)*4 + (lane >> 3);        // 0..7
    const float* Ab0 = Asm + (rg*4)*AS + ks*40;        // layer0 K-slice (40)
    const float* Ab1 = Asm + (rg*4)*AS + ks*64;        // layer1 K-slice (64)
    const float* W0p = W0s + (ks*20)*64 + cg*4;        // 20 kp per slice
    const float* W1p = W1s + (ks*32)*64 + cg*4;        // 32 kp per slice
    float* GPme = GP + ks*(32*GS);

    __syncthreads();

    for (int t = 0; t < TT; ++t) {
        const int rp = t & 1, wp = rp ^ 1;

        // ---- stage 1: A = [x(64, zero-pad) | h0[t-1](256)], batched ----
        {
            float xv[8];
#pragma unroll
            for (int i = 0; i < 8; ++i) {
                int idx = tid + i*NTH;
                int m = idx >> 6, e = idx & 63;
                xv[i] = (e < EE) ? x[(size_t)t*BB*EE + (size_t)(b0+m)*EE + e] : 0.0f;
            }
            float4 hv[8];
            const float4* src = reinterpret_cast<const float4*>(&g_h0[rp][b0*HH]);
#pragma unroll
            for (int i = 0; i < 8; ++i) hv[i] = __ldcg(src + tid + i*NTH);
#pragma unroll
            for (int i = 0; i < 8; ++i) {
                int idx = tid + i*NTH;
                Asm[(idx >> 6)*AS + (idx & 63)] = xv[i];
            }
#pragma unroll
            for (int i = 0; i < 8; ++i) {
                int idx = tid + i*NTH;
                *reinterpret_cast<float4*>(&Asm[(idx >> 6)*AS + 64 + (idx & 63)*4]) = hv[i];
            }
        }
        __syncthreads();

        // ---- layer 0 GEMM (K=320, 8-way split -> partials) ----
        {
            unsigned long long acc[4][8];
#pragma unroll
            for (int i = 0; i < 4; ++i)
#pragma unroll
                for (int j = 0; j < 8; ++j) acc[i][j] = 0ull;
            gemm_tile<10>(Ab0, W0p, acc);
#pragma unroll
            for (int i = 0; i < 4; ++i) {
                int R = rg*4 + i;
#pragma unroll
                for (int j = 0; j < 8; ++j)
                    GPme[R*GS + cg*8 + j] = pair_sum(acc[i][j]);
            }
        }
        __syncthreads();

        // ---- layer 0 elementwise: reduce partials, publish h0[t] ----
        {
            float gv[4];
#pragma unroll
            for (int g = 0; g < 4; ++g) {
                float s = B0s[g*8 + q];
#pragma unroll
                for (int p = 0; p < 8; ++p)
                    s += GP[p*(32*GS) + eb*GS + g*8 + q];
                gv[g] = s;
            }
            float iv = fsigmoid(gv[0]), fv = fsigmoid(gv[1]);
            float gg = ftanh(gv[2]),    ov = fsigmoid(gv[3]);
            c0r = fv * c0r + iv * gg;
            float hv = ov * ftanh(c0r);
            hl0 = hv;
            __stcg(&g_h0[wp][bg*HH + hg], hv);
        }
        // single barrier per step: orders h0[t] (just written) AND h1[t-1]
        // (written before each CTA's arrival here) before stage-2 reads.
        group_barrier(gb, 32u*(t+1));

        // ---- stage 2: A = [y0 = h0[t] (256) | h1[t-1] (256)], batched ----
        {
            float4 v0[8], v1[8];
            const float4* s0 = reinterpret_cast<const float4*>(&g_h0[wp][b0*HH]);
            const float4* s1 = reinterpret_cast<const float4*>(&g_h1[rp][b0*HH]);
#pragma unroll
            for (int i = 0; i < 8; ++i) v0[i] = __ldcg(s0 + tid + i*NTH);
#pragma unroll
            for (int i = 0; i < 8; ++i) v1[i] = __ldcg(s1 + tid + i*NTH);
#pragma unroll
            for (int i = 0; i < 8; ++i) {
                int idx = tid + i*NTH;
                *reinterpret_cast<float4*>(&Asm[(idx >> 6)*AS + (idx & 63)*4]) = v0[i];
            }
#pragma unroll
            for (int i = 0; i < 8; ++i) {
                int idx = tid + i*NTH;
                *reinterpret_cast<float4*>(&Asm[(idx >> 6)*AS + 256 + (idx & 63)*4]) = v1[i];
            }
        }
        __syncthreads();

        // ---- layer 1 GEMM (K=512, 8-way split) ----
        {
            unsigned long long acc[4][8];
#pragma unroll
            for (int i = 0; i < 4; ++i)
#pragma unroll
                for (int j = 0; j < 8; ++j) acc[i][j] = 0ull;
            gemm_tile<16>(Ab1, W1p, acc);
#pragma unroll
            for (int i = 0; i < 4; ++i) {
                int R = rg*4 + i;
#pragma unroll
                for (int j = 0; j < 8; ++j)
                    GPme[R*GS + cg*8 + j] = pair_sum(acc[i][j]);
            }
        }
        __syncthreads();

        // ---- layer 1 elementwise: reduce, publish h1[t] + y1 ----
        {
            float gv[4];
#pragma unroll
            for (int g = 0; g < 4; ++g) {
                float s = B1s[g*8 + q];
#pragma unroll
                for (int p = 0; p < 8; ++p)
                    s += GP[p*(32*GS) + eb*GS + g*8 + q];
                gv[g] = s;
            }
            float iv = fsigmoid(gv[0]), fv = fsigmoid(gv[1]);
            float gg = ftanh(gv[2]),    ov = fsigmoid(gv[3]);
            c1r = fv * c1r + iv * gg;
            float hv = ov * ftanh(c1r);
            hl1 = hv;
            __stcg(&g_h1[wp][bg*HH + hg], hv);
            __stcg(&g_y1[(size_t)t*BH + (size_t)bg*HH + hg], hv);
        }
        // no second barrier: next step's barrier covers h1[t] visibility.
    }

    // ---- final hn / cn ----
    out[HN_OFF +      bg*HH + hg] = hl0;
    out[HN_OFF + BH + bg*HH + hg] = hl1;
    out[CN_OFF +      bg*HH + hg] = c0r;
    out[CN_OFF + BH + bg*HH + hg] = c1r;
}

// ---------------------------------------------------------------------------
// Output projection: out = softplus(y1 @ W_out^T + b_out)
// ---------------------------------------------------------------------------
__global__ __launch_bounds__(128)
void proj_kernel(const float* __restrict__ Wout,
                 const float* __restrict__ bout,
                 float* __restrict__ out)
{
    extern __shared__ float sm[];
    float* ws = sm;
    float* ys = sm + 33*PS;
    float* bs = sm + 33*PS + 32*PS;

    const int tid = threadIdx.x;
    const int t  = blockIdx.x >> 2;
    const int b0 = (blockIdx.x & 3) * 32;

    for (int idx = tid; idx < 33*256; idx += 128) {
        int o = idx >> 8, k = idx & 255;
        ws[o*PS + k] = Wout[idx];
    }
    if (tid < 33) bs[tid] = bout[tid];
    {
        const float* ysrc = &g_y1[(size_t)t*BH + (size_t)b0*HH];
        for (int idx = tid; idx < 32*256; idx += 128) {
            int m = idx >> 8, k = idx & 255;
            ys[m*PS + k] = ysrc[idx];
        }
    }
    __syncthreads();

    for (int oidx = tid; oidx < 33*32; oidx += 128) {
        int o = oidx >> 5, m = oidx & 31;
        const float* yp = &ys[m*PS];
        const float* wpp = &ws[o*PS];
        float s = bs[o];
#pragma unroll 8
        for (int k = 0; k < 256; k += 4) {
            float4 y4 = *reinterpret_cast<const float4*>(yp + k);
            float4 w4 = *reinterpret_cast<const float4*>(wpp + k);
            s += y4.x*w4.x + y4.y*w4.y + y4.z*w4.z + y4.w*w4.w;
        }
        float sp = fmaxf(s, 0.0f) + log1pf(expf(-fabsf(s)));
        out[(size_t)t*BB*OUTD + (size_t)(b0+m)*OUTD + o] = sp;
    }
}

// ---------------------------------------------------------------------------
extern "C" void kernel_launch(void* const* d_in, const int* in_sizes, int n_in,
                              void* d_out, int out_size) {
    (void)in_sizes; (void)n_in; (void)out_size;
    const float* x    = (const float*)d_in[0];
    const float* h0   = (const float*)d_in[1];
    const float* c0   = (const float*)d_in[2];
    const float* Wih0 = (const float*)d_in[3];
    const float* Whh0 = (const float*)d_in[4];
    const float* bih0 = (const float*)d_in[5];
    const float* bhh0 = (const float*)d_in[6];
    const float* Wih1 = (const float*)d_in[7];
    const float* Whh1 = (const float*)d_in[8];
    const float* bih1 = (const float*)d_in[9];
    const float* bhh1 = (const float*)d_in[10];
    const float* Wout = (const float*)d_in[11];
    const float* bout = (const float*)d_in[12];
    float* out = (float*)d_out;

    cudaFuncSetAttribute(lstm_persistent,
                         cudaFuncAttributeMaxDynamicSharedMemorySize, SMEM_BYTES);
    cudaFuncSetAttribute(proj_kernel,
                         cudaFuncAttributeMaxDynamicSharedMemorySize, PROJ_SMEM);

    reset_kernel<<<128, 256>>>(h0);
    lstm_persistent<<<128, NTH, SMEM_BYTES>>>(
        x, c0, Wih0, Whh0, bih0, bhh0, Wih1, Whh1, bih1, bhh1, out);
    proj_kernel<<<4096, 128, PROJ_SMEM>>>(Wout, bout, out);
}